// round 15
// baseline (speedup 1.0000x reference)
#include <cuda_runtime.h>
#include <cstdint>

__device__ float g_lig_proj[512 * 512];
__device__ float g_rec_proj[512 * 512];

#define D 512
#define BM 32
#define BN 32
#define BK 32
#define NKT (D / BK)    // 16
#define JBLK 64

__device__ __forceinline__ uint32_t f2tf32(float x) {
    uint32_t r;
    asm("cvt.rna.tf32.f32 %0, %1;" : "=r"(r) : "f"(x));
    return r;
}

__device__ __forceinline__ void mma_tf32(float* d, const uint32_t* a, const uint32_t* b) {
    asm volatile(
        "mma.sync.aligned.m16n8k8.row.col.f32.tf32.tf32.f32 "
        "{%0,%1,%2,%3}, {%4,%5,%6,%7}, {%8,%9}, {%0,%1,%2,%3};"
        : "+f"(d[0]), "+f"(d[1]), "+f"(d[2]), "+f"(d[3])
        : "r"(a[0]), "r"(a[1]), "r"(a[2]), "r"(a[3]), "r"(b[0]), "r"(b[1]));
}

// C[i,o] = sum_k A[i,k] * W[o, w_off + k] (+ bias for receptor).
// tf32 tensor cores, hi/lo compensation, scatter-time conversion.
// 32x32 tiles -> 512 blocks (3.5/SM) for latency hiding; 128 threads (2m x 2n warps);
// smem 16KB, single-buffered (two syncs/iter), register prefetch of next tile.
__global__ __launch_bounds__(128) void proj_gemm_kernel(
    const float* __restrict__ lig,
    const float* __restrict__ rec,
    const float* __restrict__ W,
    const float* __restrict__ bias)
{
    __shared__ uint32_t SaHi[BM * BK];   // 4KB, fragment-ordered
    __shared__ uint32_t SaLo[BM * BK];
    __shared__ uint32_t SbHi[BN * BK];
    __shared__ uint32_t SbLo[BN * BK];

    const int z = blockIdx.z;
    const float* A = (z == 0) ? lig : rec;
    float* C = (z == 0) ? g_lig_proj : g_rec_proj;
    const int w_off4 = (z == 0) ? 0 : (D / 4);

    const int tid = threadIdx.x;
    const int lane = tid & 31;
    const int wid = tid >> 5;
    const int mwarp = wid >> 1;     // 0..1 -> m16 each
    const int nwarp = wid & 1;      // 0..1 -> n16 each
    const int i0 = blockIdx.y * BM;
    const int o0 = blockIdx.x * BN;

    const int r = lane >> 2;        // fragment row 0..7
    const int cq = lane & 3;        // fragment col-quad 0..3

    const float4* A4 = reinterpret_cast<const float4*>(A);
    const float4* W4 = reinterpret_cast<const float4*>(W);

    float acc[2][4] = {};           // [nt][quad] — warp owns m16 x n16

    // Tile = 32 rows x 8 f4-cols = 256 float4. 128 threads -> 2 each (f and f+128).
    auto scatA = [&](int row, int c4, float4 v) {
        #pragma unroll
        for (int q = 0; q < 4; q++) {
            float val = (q == 0) ? v.x : (q == 1) ? v.y : (q == 2) ? v.z : v.w;
            int kl = c4 * 4 + q;
            int mtile = row >> 4, ktile = kl >> 3;
            int rr = row & 15, cc = kl & 7;
            int ln = ((rr & 7) << 2) | (cc & 3);
            int idx = ((cc & 4) >> 1) | ((rr & 8) >> 3);
            int off = ((mtile * 4 + ktile) * 32 + ln) * 4 + idx;
            uint32_t hi = f2tf32(val);
            SaHi[off] = hi;
            SaLo[off] = f2tf32(val - __uint_as_float(hi));
        }
    };
    auto scatB = [&](int row, int c4, float4 v) {
        #pragma unroll
        for (int q = 0; q < 4; q++) {
            float val = (q == 0) ? v.x : (q == 1) ? v.y : (q == 2) ? v.z : v.w;
            int kl = c4 * 4 + q;
            int ntile = row >> 3, ktile = kl >> 3;
            int n = row & 7, cc = kl & 7;
            int ln = (n << 2) | (cc & 3);
            int idx = (cc & 4) >> 2;
            int off = ((ntile * 4 + ktile) * 32 + ln) * 2 + idx;
            uint32_t hi = f2tf32(val);
            SbHi[off] = hi;
            SbLo[off] = f2tf32(val - __uint_as_float(hi));
        }
    };

    // thread's two f4 slots in the 256-f4 tile
    const int ra0 = tid >> 3,        ca0 = tid & 7;          // f = tid
    const int ra1 = (tid + 128) >> 3, ca1 = (tid + 128) & 7; // f = tid + 128

    // Prologue: tile 0
    {
        float4 a0 = A4[(size_t)(i0 + ra0) * (D / 4) + ca0];
        float4 a1 = A4[(size_t)(i0 + ra1) * (D / 4) + ca1];
        float4 b0 = W4[(size_t)(o0 + ra0) * (2 * D / 4) + w_off4 + ca0];
        float4 b1 = W4[(size_t)(o0 + ra1) * (2 * D / 4) + w_off4 + ca1];
        scatA(ra0, ca0, a0); scatA(ra1, ca1, a1);
        scatB(ra0, ca0, b0); scatB(ra1, ca1, b1);
    }
    __syncthreads();

    for (int t = 0; t < NKT; t++) {
        float4 a0, a1, b0, b1;
        if (t + 1 < NKT) {
            const int kc4 = (t + 1) * (BK / 4);
            a0 = A4[(size_t)(i0 + ra0) * (D / 4) + kc4 + ca0];
            a1 = A4[(size_t)(i0 + ra1) * (D / 4) + kc4 + ca1];
            b0 = W4[(size_t)(o0 + ra0) * (2 * D / 4) + w_off4 + kc4 + ca0];
            b1 = W4[(size_t)(o0 + ra1) * (2 * D / 4) + w_off4 + kc4 + ca1];
        }

        #pragma unroll
        for (int k8 = 0; k8 < 4; k8++) {
            uint32_t ahi[4], alo[4], bhi[2][2], blo[2][2];
            {
                int base = ((mwarp * 4 + k8) * 32 + lane) * 4;
                *reinterpret_cast<uint4*>(ahi) = *reinterpret_cast<const uint4*>(&SaHi[base]);
                *reinterpret_cast<uint4*>(alo) = *reinterpret_cast<const uint4*>(&SaLo[base]);
            }
            #pragma unroll
            for (int nt = 0; nt < 2; nt++) {
                int base = (((nwarp * 2 + nt) * 4 + k8) * 32 + lane) * 2;
                *reinterpret_cast<uint2*>(bhi[nt]) = *reinterpret_cast<const uint2*>(&SbHi[base]);
                *reinterpret_cast<uint2*>(blo[nt]) = *reinterpret_cast<const uint2*>(&SbLo[base]);
            }
            #pragma unroll
            for (int nt = 0; nt < 2; nt++) {
                mma_tf32(acc[nt], ahi, bhi[nt]);
                mma_tf32(acc[nt], alo, bhi[nt]);
                mma_tf32(acc[nt], ahi, blo[nt]);
            }
        }

        __syncthreads();
        if (t + 1 < NKT) {
            scatA(ra0, ca0, a0); scatA(ra1, ca1, a1);
            scatB(ra0, ca0, b0); scatB(ra1, ca1, b1);
            __syncthreads();
        }
    }

    // Epilogue: c0,c1 -> (row, col..col+1); c2,c3 -> (row+8, ...)
    #pragma unroll
    for (int nt = 0; nt < 2; nt++) {
        int row = i0 + mwarp * 16 + r;
        int col = o0 + nwarp * 16 + nt * 8 + 2 * cq;
        float bv0 = 0.f, bv1 = 0.f;
        if (z == 1) { bv0 = bias[col]; bv1 = bias[col + 1]; }
        float2 lo_pair = make_float2(acc[nt][0] + bv0, acc[nt][1] + bv1);
        float2 hi_pair = make_float2(acc[nt][2] + bv0, acc[nt][3] + bv1);
        *reinterpret_cast<float2*>(&C[(size_t)row * D + col]) = lo_pair;
        *reinterpret_cast<float2*>(&C[(size_t)(row + 8) * D + col]) = hi_pair;
    }

#if __CUDA_ARCH__ >= 900
    cudaTriggerProgrammaticLaunchCompletion();
#endif
}

// out[i, j, :] = lig_proj[i, :] + rec_proj[j, :]
// Exact best-measured config (R11, 83.2us): block = (1 i, 64 j), 128 threads, 4096 blocks.
__global__ __launch_bounds__(128) void pair_add_kernel(float4* __restrict__ out)
{
    const int c = threadIdx.x;            // float4 column 0..127
    const int i = blockIdx.y;
    const int j0 = blockIdx.x * JBLK;

    const float4* lig = reinterpret_cast<const float4*>(g_lig_proj);
    const float4* rec = reinterpret_cast<const float4*>(g_rec_proj);

    const float4* ap = lig + i * 128 + c;
    const float4* rp = rec + (size_t)j0 * 128 + c;
    float4* op = out + ((size_t)i * D + j0) * 128 + c;

#if __CUDA_ARCH__ >= 900
    cudaGridDependencySynchronize();
#endif

    const float4 a = *ap;

    #pragma unroll 8
    for (int jj = 0; jj < JBLK; jj++) {
        float4 r = __ldg(rp + (size_t)jj * 128);
        float4 o;
        o.x = a.x + r.x;
        o.y = a.y + r.y;
        o.z = a.z + r.z;
        o.w = a.w + r.w;
        __stcs(op + (size_t)jj * 128, o);
    }
}

extern "C" void kernel_launch(void* const* d_in, const int* in_sizes, int n_in,
                              void* d_out, int out_size)
{
    const float* lig = (const float*)d_in[0];   // (512, 512)
    const float* rec = (const float*)d_in[1];   // (512, 512)
    const float* W   = (const float*)d_in[2];   // (512, 1024)
    const float* b   = (const float*)d_in[3];   // (512,)
    float* out = (float*)d_out;                 // (512, 512, 512)

    dim3 ggrd(D / BN, D / BM, 2);   // 16 x 16 x 2 = 512 blocks
    proj_gemm_kernel<<<ggrd, 128>>>(lig, rec, W, b);

    // Add kernel with PDL: overlaps launch/ramp with the GEMM drain.
    cudaLaunchConfig_t cfg = {};
    cfg.gridDim = dim3(D / JBLK, D, 1);   // 8 x 512 = 4096 blocks
    cfg.blockDim = dim3(128, 1, 1);
    cfg.dynamicSmemBytes = 0;
    cfg.stream = 0;
    cudaLaunchAttribute attrs[1];
    attrs[0].id = cudaLaunchAttributeProgrammaticStreamSerialization;
    attrs[0].val.programmaticStreamSerializationAllowed = 1;
    cfg.attrs = attrs;
    cfg.numAttrs = 1;
    cudaLaunchKernelEx(&cfg, pair_add_kernel, reinterpret_cast<float4*>(out));
}

// round 17
// speedup vs baseline: 1.1273x; 1.1273x over previous
#include <cuda_runtime.h>
#include <cstdint>

__device__ float g_lig_proj[512 * 512];
__device__ float g_rec_proj[512 * 512];

#define D 512
#define BM 64
#define BN 64
#define BK 32
#define KSPLIT 256
#define NKT (KSPLIT / BK)   // 8
#define JBLK 64

__device__ __forceinline__ uint32_t f2tf32(float x) {
    uint32_t r;
    asm("cvt.rna.tf32.f32 %0, %1;" : "=r"(r) : "f"(x));
    return r;
}

__device__ __forceinline__ void mma_tf32(float* d, const uint32_t* a, const uint32_t* b) {
    asm volatile(
        "mma.sync.aligned.m16n8k8.row.col.f32.tf32.tf32.f32 "
        "{%0,%1,%2,%3}, {%4,%5,%6,%7}, {%8,%9}, {%0,%1,%2,%3};"
        : "+f"(d[0]), "+f"(d[1]), "+f"(d[2]), "+f"(d[3])
        : "r"(a[0]), "r"(a[1]), "r"(a[2]), "r"(a[3]), "r"(b[0]), "r"(b[1]));
}

// Split-K=2 tf32 GEMM, fold via atomicAdd epilogue onto zeroed buffers.
// Exactly 2 contributions per element: (0+a)+b == (0+b)+a bitwise -> deterministic.
// grid (8,8,4) = 256 blocks, 8 K-iterations each.
__global__ __launch_bounds__(256) void proj_gemm_kernel(
    const float* __restrict__ lig,
    const float* __restrict__ rec,
    const float* __restrict__ W,
    const float* __restrict__ bias)
{
    __shared__ uint32_t SaHi[BM * BK];
    __shared__ uint32_t SaLo[BM * BK];
    __shared__ uint32_t SbHi[BN * BK];
    __shared__ uint32_t SbLo[BN * BK];

    const int bz = blockIdx.z;      // 0..3
    const int z  = bz >> 1;         // 0 = ligand, 1 = receptor
    const int ks = bz & 1;          // K chunk
    const float* A = (z == 0) ? lig : rec;
    float* C = (z == 0) ? g_lig_proj : g_rec_proj;
    const int a_off4 = ks * (KSPLIT / 4);
    const int w_off4 = ((z == 0) ? 0 : (D / 4)) + a_off4;

    const int tid = threadIdx.x;
    const int lane = tid & 31;
    const int wid = tid >> 5;
    const int mwarp = wid >> 2;     // 0..1
    const int nwarp = wid & 3;      // 0..3
    const int i0 = blockIdx.y * BM;
    const int o0 = blockIdx.x * BN;

    const int lr0 = tid >> 3;       // 0..31
    const int lc  = tid & 7;        // float4 col 0..7
    const float4* A4 = reinterpret_cast<const float4*>(A);
    const float4* W4 = reinterpret_cast<const float4*>(W);

    float acc[2][2][4] = {};

    auto scatA = [&](int r, float4 v) {
        #pragma unroll
        for (int q = 0; q < 4; q++) {
            float val = (q == 0) ? v.x : (q == 1) ? v.y : (q == 2) ? v.z : v.w;
            int kl = lc * 4 + q;
            int mtile = r >> 4, ktile = kl >> 3;
            int rr = r & 15, cc = kl & 7;
            int ln = ((rr & 7) << 2) | (cc & 3);
            int idx = ((cc & 4) >> 1) | ((rr & 8) >> 3);
            int off = ((mtile * 4 + ktile) * 32 + ln) * 4 + idx;
            uint32_t hi = f2tf32(val);
            SaHi[off] = hi;
            SaLo[off] = f2tf32(val - __uint_as_float(hi));
        }
    };
    auto scatB = [&](int r, float4 v) {
        #pragma unroll
        for (int q = 0; q < 4; q++) {
            float val = (q == 0) ? v.x : (q == 1) ? v.y : (q == 2) ? v.z : v.w;
            int kl = lc * 4 + q;
            int ntile = r >> 3, ktile = kl >> 3;
            int n = r & 7, cc = kl & 7;
            int ln = (n << 2) | (cc & 3);
            int idx = (cc & 4) >> 2;
            int off = ((ntile * 4 + ktile) * 32 + ln) * 2 + idx;
            uint32_t hi = f2tf32(val);
            SbHi[off] = hi;
            SbLo[off] = f2tf32(val - __uint_as_float(hi));
        }
    };

    {
        float4 va0 = A4[(size_t)(i0 + lr0)      * (D / 4) + a_off4 + lc];
        float4 va1 = A4[(size_t)(i0 + lr0 + 32) * (D / 4) + a_off4 + lc];
        float4 vb0 = W4[(size_t)(o0 + lr0)      * (2 * D / 4) + w_off4 + lc];
        float4 vb1 = W4[(size_t)(o0 + lr0 + 32) * (2 * D / 4) + w_off4 + lc];
        scatA(lr0, va0); scatA(lr0 + 32, va1);
        scatB(lr0, vb0); scatB(lr0 + 32, vb1);
    }
    __syncthreads();

    for (int t = 0; t < NKT; t++) {
        float4 va0, va1, vb0, vb1;
        if (t + 1 < NKT) {
            const int kc4 = (t + 1) * (BK / 4);
            va0 = A4[(size_t)(i0 + lr0)      * (D / 4) + a_off4 + kc4 + lc];
            va1 = A4[(size_t)(i0 + lr0 + 32) * (D / 4) + a_off4 + kc4 + lc];
            vb0 = W4[(size_t)(o0 + lr0)      * (2 * D / 4) + w_off4 + kc4 + lc];
            vb1 = W4[(size_t)(o0 + lr0 + 32) * (2 * D / 4) + w_off4 + kc4 + lc];
        }

        #pragma unroll
        for (int k8 = 0; k8 < 4; k8++) {
            uint32_t ahi[2][4], alo[2][4], bhi[2][2], blo[2][2];
            #pragma unroll
            for (int mt = 0; mt < 2; mt++) {
                int base = (((mwarp * 2 + mt) * 4 + k8) * 32 + lane) * 4;
                *reinterpret_cast<uint4*>(ahi[mt]) = *reinterpret_cast<const uint4*>(&SaHi[base]);
                *reinterpret_cast<uint4*>(alo[mt]) = *reinterpret_cast<const uint4*>(&SaLo[base]);
            }
            #pragma unroll
            for (int nt = 0; nt < 2; nt++) {
                int base = (((nwarp * 2 + nt) * 4 + k8) * 32 + lane) * 2;
                *reinterpret_cast<uint2*>(bhi[nt]) = *reinterpret_cast<const uint2*>(&SbHi[base]);
                *reinterpret_cast<uint2*>(blo[nt]) = *reinterpret_cast<const uint2*>(&SbLo[base]);
            }
            #pragma unroll
            for (int mt = 0; mt < 2; mt++)
                #pragma unroll
                for (int nt = 0; nt < 2; nt++) {
                    mma_tf32(acc[mt][nt], ahi[mt], bhi[nt]);
                    mma_tf32(acc[mt][nt], alo[mt], bhi[nt]);
                    mma_tf32(acc[mt][nt], ahi[mt], blo[nt]);
                }
        }

        __syncthreads();
        if (t + 1 < NKT) {
            scatA(lr0, va0); scatA(lr0 + 32, va1);
            scatB(lr0, vb0); scatB(lr0 + 32, vb1);
            __syncthreads();
        }
    }

    // Epilogue: fold partial into C via atomicAdd (REDG, no return).
    // Bias added once (z==1, ks==0 chunk).
    const bool add_bias = (z == 1) && (ks == 0);
    #pragma unroll
    for (int mt = 0; mt < 2; mt++) {
        #pragma unroll
        for (int nt = 0; nt < 2; nt++) {
            int row = i0 + mwarp * 32 + mt * 16 + (lane >> 2);
            int col = o0 + nwarp * 16 + nt * 8 + 2 * (lane & 3);
            float bv0 = 0.f, bv1 = 0.f;
            if (add_bias) { bv0 = bias[col]; bv1 = bias[col + 1]; }
            atomicAdd(&C[(size_t)row * D + col],           acc[mt][nt][0] + bv0);
            atomicAdd(&C[(size_t)row * D + col + 1],       acc[mt][nt][1] + bv1);
            atomicAdd(&C[(size_t)(row + 8) * D + col],     acc[mt][nt][2] + bv0);
            atomicAdd(&C[(size_t)(row + 8) * D + col + 1], acc[mt][nt][3] + bv1);
        }
    }

#if __CUDA_ARCH__ >= 900
    cudaTriggerProgrammaticLaunchCompletion();
#endif
}

// out[i, j, :] = lig_proj[i, :] + rec_proj[j, :]
// Exact best-measured config (R11, 83.2us): block = (1 i, 64 j), 128 threads, 4096 blocks.
__global__ __launch_bounds__(128) void pair_add_kernel(float4* __restrict__ out)
{
    const int c = threadIdx.x;            // float4 column 0..127
    const int i = blockIdx.y;
    const int j0 = blockIdx.x * JBLK;

    const float4* lig = reinterpret_cast<const float4*>(g_lig_proj);
    const float4* rec = reinterpret_cast<const float4*>(g_rec_proj);

    const float4* ap = lig + i * 128 + c;
    const float4* rp = rec + (size_t)j0 * 128 + c;
    float4* op = out + ((size_t)i * D + j0) * 128 + c;

#if __CUDA_ARCH__ >= 900
    cudaGridDependencySynchronize();
#endif

    const float4 a = *ap;

    #pragma unroll 8
    for (int jj = 0; jj < JBLK; jj++) {
        float4 r = __ldg(rp + (size_t)jj * 128);
        float4 o;
        o.x = a.x + r.x;
        o.y = a.y + r.y;
        o.z = a.z + r.z;
        o.w = a.w + r.w;
        __stcs(op + (size_t)jj * 128, o);
    }
}

extern "C" void kernel_launch(void* const* d_in, const int* in_sizes, int n_in,
                              void* d_out, int out_size)
{
    const float* lig = (const float*)d_in[0];   // (512, 512)
    const float* rec = (const float*)d_in[1];   // (512, 512)
    const float* W   = (const float*)d_in[2];   // (512, 1024)
    const float* b   = (const float*)d_in[3];   // (512,)
    float* out = (float*)d_out;                 // (512, 512, 512)

    // Zero the projection accumulators (graph-capturable async memset, ~2MB total).
    float* lig_sym = nullptr;
    float* rec_sym = nullptr;
    cudaGetSymbolAddress((void**)&lig_sym, g_lig_proj);
    cudaGetSymbolAddress((void**)&rec_sym, g_rec_proj);
    cudaMemsetAsync(lig_sym, 0, 512 * 512 * sizeof(float), 0);
    cudaMemsetAsync(rec_sym, 0, 512 * 512 * sizeof(float), 0);

    dim3 ggrd(D / BN, D / BM, 4);   // 8 x 8 x 4 = 256 blocks (split-K=2)
    proj_gemm_kernel<<<ggrd, 256>>>(lig, rec, W, b);

    // Add kernel with PDL: overlaps launch/ramp with the GEMM drain.
    cudaLaunchConfig_t cfg = {};
    cfg.gridDim = dim3(D / JBLK, D, 1);   // 8 x 512 = 4096 blocks
    cfg.blockDim = dim3(128, 1, 1);
    cfg.dynamicSmemBytes = 0;
    cfg.stream = 0;
    cudaLaunchAttribute attrs[1];
    attrs[0].id = cudaLaunchAttributeProgrammaticStreamSerialization;
    attrs[0].val.programmaticStreamSerializationAllowed = 1;
    cfg.attrs = attrs;
    cfg.numAttrs = 1;
    cudaLaunchKernelEx(&cfg, pair_add_kernel, reinterpret_cast<float4*>(out));
}